// round 1
// baseline (speedup 1.0000x reference)
#include <cuda_runtime.h>
#include <math.h>

// Problem dims (fixed by the dataset)
#define FDIM 1024          // feature dim
#define NK   256           // num_bpe
#define NL   8             // num_gauss
#define KLD  (NK*NL)       // 2048 fused k*l dim
#define KC   (2*FDIM)      // 2048 GEMM reduction dim ([X | X^2])
#define BTD  32768         // B*T rows

// GEMM tiling
#define BM 128
#define BN 128
#define BKK 8

// Scratch: combined weights W[KL][2F] and per-(k,l) bias. Static device
// globals (allocation-free per harness rules). 16 MB + 8 KB.
__device__ float g_W[(size_t)KLD * KC];
__device__ float g_bias[KLD];

// ---------------------------------------------------------------------------
// prep1: one block per kl. Builds W rows and bias (without log_w term).
//   W[kl][f]      = mu * exp(-log_cov)          (xm term)
//   W[kl][F + f]  = -0.5 * exp(-log_cov)        (x2 term)
//   bias0[kl]     = -0.5*F*log(2pi) - 0.5*sum(log_cov) - 0.5*sum(mu^2*iv)
// ---------------------------------------------------------------------------
__global__ void prep1(const float* __restrict__ mu,
                      const float* __restrict__ log_cov) {
    int kl = blockIdx.x;
    int tid = threadIdx.x;
    const float* mu_r = mu + (size_t)kl * FDIM;
    const float* lc_r = log_cov + (size_t)kl * FDIM;
    float* w_r = g_W + (size_t)kl * KC;

    float s_lc = 0.0f, s_m2 = 0.0f;
    for (int f = tid; f < FDIM; f += blockDim.x) {
        float lc = lc_r[f];
        float iv = expf(-lc);
        float m  = mu_r[f];
        w_r[f]        = m * iv;
        w_r[FDIM + f] = -0.5f * iv;
        s_lc += lc;
        s_m2 += m * m * iv;
    }

    __shared__ float sh0[256];
    __shared__ float sh1[256];
    sh0[tid] = s_lc;
    sh1[tid] = s_m2;
    __syncthreads();
    for (int s = 128; s > 0; s >>= 1) {
        if (tid < s) {
            sh0[tid] += sh0[tid + s];
            sh1[tid] += sh1[tid + s];
        }
        __syncthreads();
    }
    if (tid == 0) {
        const float LOG_2PI = 1.8378770664093453f;
        g_bias[kl] = -0.5f * (float)FDIM * LOG_2PI - 0.5f * sh0[0] - 0.5f * sh1[0];
    }
}

// ---------------------------------------------------------------------------
// prep2: one thread per k. Adds log_softmax(log_pi) to bias.
// ---------------------------------------------------------------------------
__global__ void prep2(const float* __restrict__ log_pi) {
    int k = blockIdx.x * blockDim.x + threadIdx.x;
    if (k >= NK) return;
    float v[NL];
    float mx = -INFINITY;
#pragma unroll
    for (int l = 0; l < NL; l++) {
        v[l] = log_pi[k * NL + l];
        mx = fmaxf(mx, v[l]);
    }
    float s = 0.0f;
#pragma unroll
    for (int l = 0; l < NL; l++) s += expf(v[l] - mx);
    float lse = mx + logf(s);
#pragma unroll
    for (int l = 0; l < NL; l++) g_bias[k * NL + l] += v[l] - lse;
}

// ---------------------------------------------------------------------------
// Main fused kernel: SGEMM  [BT x 2F] @ [2F x KL]^T-ish  + logsumexp over L=8.
// A tile built on the fly: columns [0,F) = X, [F,2F) = X^2.
// 128x128 block tile, 8x8 thread microtile, BK=8, 256 threads.
// Each thread's 8 output columns are exactly one k's 8 l-values, so the
// logsumexp epilogue is thread-local (no cross-thread reduction).
// ---------------------------------------------------------------------------
__global__ __launch_bounds__(256) void gmm_main(const float* __restrict__ X,
                                                float* __restrict__ out) {
    __shared__ float As[BKK][BM];
    __shared__ float Bs[BKK][BN];

    int tid = threadIdx.x;
    int tx = tid & 15;        // 0..15  -> column group (8 cols = one k)
    int ty = tid >> 4;        // 0..15  -> row group (8 rows)

    int loadRow = tid >> 1;         // 0..127
    int loadCol = (tid & 1) * 4;    // 0 or 4

    int rowBase = blockIdx.y * BM;
    int colBase = blockIdx.x * BN;

    const float* Arow = X + (size_t)(rowBase + loadRow) * FDIM;
    const float* Brow = g_W + (size_t)(colBase + loadRow) * KC;

    float acc[8][8];
#pragma unroll
    for (int i = 0; i < 8; i++)
#pragma unroll
        for (int j = 0; j < 8; j++) acc[i][j] = 0.0f;

    for (int kk = 0; kk < KC; kk += BKK) {
        int c0 = kk + loadCol;
        // A element (row, c) = c < F ? X[row,c] : X[row,c-F]^2.
        // c0 is 4-aligned and the F boundary is 8-aligned, so a float4 never
        // straddles the boundary.
        float4 av;
        if (c0 < FDIM) {
            av = *reinterpret_cast<const float4*>(Arow + c0);
        } else {
            float4 x = *reinterpret_cast<const float4*>(Arow + (c0 - FDIM));
            av = make_float4(x.x * x.x, x.y * x.y, x.z * x.z, x.w * x.w);
        }
        float4 bv = *reinterpret_cast<const float4*>(Brow + c0);

        As[loadCol + 0][loadRow] = av.x;
        As[loadCol + 1][loadRow] = av.y;
        As[loadCol + 2][loadRow] = av.z;
        As[loadCol + 3][loadRow] = av.w;
        Bs[loadCol + 0][loadRow] = bv.x;
        Bs[loadCol + 1][loadRow] = bv.y;
        Bs[loadCol + 2][loadRow] = bv.z;
        Bs[loadCol + 3][loadRow] = bv.w;
        __syncthreads();

#pragma unroll
        for (int k = 0; k < BKK; k++) {
            float4 a0 = *reinterpret_cast<const float4*>(&As[k][ty * 8]);
            float4 a1 = *reinterpret_cast<const float4*>(&As[k][ty * 8 + 4]);
            float4 b0 = *reinterpret_cast<const float4*>(&Bs[k][tx * 8]);
            float4 b1 = *reinterpret_cast<const float4*>(&Bs[k][tx * 8 + 4]);
            float a[8] = {a0.x, a0.y, a0.z, a0.w, a1.x, a1.y, a1.z, a1.w};
            float b[8] = {b0.x, b0.y, b0.z, b0.w, b1.x, b1.y, b1.z, b1.w};
#pragma unroll
            for (int i = 0; i < 8; i++)
#pragma unroll
                for (int j = 0; j < 8; j++) acc[i][j] = fmaf(a[i], b[j], acc[i][j]);
        }
        __syncthreads();
    }

    // Epilogue: logits = acc + bias[col]; logsumexp over the thread's 8 cols.
    float bj[8];
#pragma unroll
    for (int j = 0; j < 8; j++) bj[j] = g_bias[colBase + tx * 8 + j];

    int kOut = (colBase >> 3) + tx;  // global k index

#pragma unroll
    for (int i = 0; i < 8; i++) {
        float l[8];
        float mx = -INFINITY;
#pragma unroll
        for (int j = 0; j < 8; j++) {
            l[j] = acc[i][j] + bj[j];
            mx = fmaxf(mx, l[j]);
        }
        float s = 0.0f;
#pragma unroll
        for (int j = 0; j < 8; j++) s += __expf(l[j] - mx);
        out[(size_t)(rowBase + ty * 8 + i) * NK + kOut] = mx + __logf(s);
    }
}

// ---------------------------------------------------------------------------
// Launch: prep1 -> prep2 -> fused GEMM+logsumexp. All plain launches on the
// default stream; graph-capturable, allocation-free.
// Input order (metadata): X, mu, log_cov, log_pi.
// ---------------------------------------------------------------------------
extern "C" void kernel_launch(void* const* d_in, const int* in_sizes, int n_in,
                              void* d_out, int out_size) {
    const float* X       = (const float*)d_in[0];
    const float* mu      = (const float*)d_in[1];
    const float* log_cov = (const float*)d_in[2];
    const float* log_pi  = (const float*)d_in[3];
    float* out = (float*)d_out;

    prep1<<<KLD, 256>>>(mu, log_cov);
    prep2<<<1, 256>>>(log_pi);

    dim3 grid(KLD / BN, BTD / BM);
    gmm_main<<<grid, 256>>>(X, out);
}

// round 3
// speedup vs baseline: 7.8775x; 7.8775x over previous
#include <cuda_runtime.h>
#include <cuda_bf16.h>
#include <math.h>
#include <stdint.h>

// ---------------------------------------------------------------- problem dims
#define FDIM 1024
#define NK   256
#define NL   8
#define KLD  2048            // NK*NL
#define KC   2048            // GEMM K = [X | X^2]
#define BTD  32768           // B*T

// ---------------------------------------------------------------- GEMM tiling
#define BM 128
#define BN 128
#define BK 64                // bf16 elems per K-stage (128 B per row)
#define KITERS (KC / BK)     // 32
#define NTHREADS 256
#define STAGES 3
#define STAGE_BYTES (32 * 1024)          // A 16KB + B 16KB
#define SM_BIAS_OFF (STAGES * STAGE_BYTES)
#define SMEM_TOTAL  (SM_BIAS_OFF + 512)  // 98816 B

// ---------------------------------------------------------------- device scratch
__device__ __nv_bfloat16 g_Ah[(size_t)BTD * KC];   // 128 MB  [X | X^2] bf16
__device__ __nv_bfloat16 g_Wh[(size_t)KLD * KC];   // 8 MB    [mu*iv | -0.5*iv] bf16
__device__ float         g_bias[KLD];

// ---------------------------------------------------------------- asm helpers
__device__ __forceinline__ uint32_t smem_u32(const void* p) {
    uint32_t a;
    asm("{ .reg .u64 t; cvta.to.shared.u64 t, %1; cvt.u32.u64 %0, t; }" : "=r"(a) : "l"(p));
    return a;
}
__device__ __forceinline__ void cp16(uint32_t dst, const void* src) {
    asm volatile("cp.async.cg.shared.global [%0], [%1], 16;" :: "r"(dst), "l"(src));
}
#define CP_COMMIT() asm volatile("cp.async.commit_group;" ::: "memory")
#define CP_WAIT(n)  asm volatile("cp.async.wait_group %0;" :: "n"(n) : "memory")

#define LDSM4(r, addr)                                                          \
    asm volatile("ldmatrix.sync.aligned.m8n8.x4.shared.b16 {%0,%1,%2,%3}, [%4];" \
        : "=r"((r)[0]), "=r"((r)[1]), "=r"((r)[2]), "=r"((r)[3]) : "r"(addr))

#define MMA16816(c, a, b0, b1)                                                  \
    asm volatile("mma.sync.aligned.m16n8k16.row.col.f32.bf16.bf16.f32 "          \
        "{%0,%1,%2,%3}, {%4,%5,%6,%7}, {%8,%9}, {%0,%1,%2,%3};"                  \
        : "+f"((c)[0]), "+f"((c)[1]), "+f"((c)[2]), "+f"((c)[3])                 \
        : "r"((a)[0]), "r"((a)[1]), "r"((a)[2]), "r"((a)[3]), "r"(b0), "r"(b1))

// ---------------------------------------------------------------- fast math
__device__ __forceinline__ float fast_exp(float u) {   // e^u, u <= 0
    u = fmaxf(u, -60.0f);
    float z  = u * 1.4426950408889634f;
    float nf = rintf(z);
    float w  = fmaf(nf, -0.6931471805599453f, u);
    float p  = fmaf(w, 0.041666668f, 0.16666667f);
    p = fmaf(w, p, 0.5f);
    p = fmaf(w, p, 1.0f);
    p = fmaf(w, p, 1.0f);
    return p * __int_as_float(((int)nf + 127) << 23);
}
__device__ __forceinline__ float fast_log(float s) {   // ln(s), s in [1, 16]
    int ib = __float_as_int(s);
    int e  = (ib - 0x3f3504f3) >> 23;
    float m = __int_as_float(ib - (e << 23));
    float t = m - 1.0f;
    float p = -0.125f;
    p = fmaf(p, t, 0.14285714f);
    p = fmaf(p, t, -0.16666667f);
    p = fmaf(p, t, 0.2f);
    p = fmaf(p, t, -0.25f);
    p = fmaf(p, t, 0.33333333f);
    p = fmaf(p, t, -0.5f);
    p = fmaf(p, t, 1.0f);
    p = p * t;
    return fmaf((float)e, 0.6931471805599453f, p);
}

// ---------------------------------------------------------------- prep kernels
__global__ void prepA(const float* __restrict__ X) {
    size_t i = (size_t)blockIdx.x * blockDim.x + threadIdx.x;   // one float4 of X
    float4 v = reinterpret_cast<const float4*>(X)[i];
    size_t row = i >> 8;                   // FDIM/4 = 256 float4 per row
    size_t c   = (i & 255) << 2;
    __nv_bfloat16* a = g_Ah + row * KC;
    *reinterpret_cast<__nv_bfloat162*>(a + c)            = __floats2bfloat162_rn(v.x, v.y);
    *reinterpret_cast<__nv_bfloat162*>(a + c + 2)        = __floats2bfloat162_rn(v.z, v.w);
    *reinterpret_cast<__nv_bfloat162*>(a + FDIM + c)     = __floats2bfloat162_rn(v.x * v.x, v.y * v.y);
    *reinterpret_cast<__nv_bfloat162*>(a + FDIM + c + 2) = __floats2bfloat162_rn(v.z * v.z, v.w * v.w);
}

__global__ void prepW(const float* __restrict__ mu, const float* __restrict__ log_cov) {
    int kl = blockIdx.x, t = threadIdx.x;
    const float* mu_r = mu + (size_t)kl * FDIM;
    const float* lc_r = log_cov + (size_t)kl * FDIM;
    __nv_bfloat16* w_r = g_Wh + (size_t)kl * KC;
    float s_lc = 0.f, s_m2 = 0.f;
    for (int f = t; f < FDIM; f += 256) {
        float lc = lc_r[f];
        float iv = expf(-lc);
        float m  = mu_r[f];
        w_r[f]        = __float2bfloat16(m * iv);
        w_r[FDIM + f] = __float2bfloat16(-0.5f * iv);
        s_lc += lc;
        s_m2 += m * m * iv;
    }
    __shared__ float sh0[256], sh1[256];
    sh0[t] = s_lc; sh1[t] = s_m2;
    __syncthreads();
    for (int s = 128; s > 0; s >>= 1) {
        if (t < s) { sh0[t] += sh0[t + s]; sh1[t] += sh1[t + s]; }
        __syncthreads();
    }
    if (t == 0)
        g_bias[kl] = -0.5f * (float)FDIM * 1.8378770664093453f - 0.5f * sh0[0] - 0.5f * sh1[0];
}

__global__ void prepPi(const float* __restrict__ log_pi) {
    int k = blockIdx.x * blockDim.x + threadIdx.x;
    if (k >= NK) return;
    float v[NL], mx = -INFINITY;
#pragma unroll
    for (int l = 0; l < NL; l++) { v[l] = log_pi[k * NL + l]; mx = fmaxf(mx, v[l]); }
    float s = 0.f;
#pragma unroll
    for (int l = 0; l < NL; l++) s += expf(v[l] - mx);
    float lse = mx + logf(s);
#pragma unroll
    for (int l = 0; l < NL; l++) g_bias[k * NL + l] += v[l] - lse;
}

// ---------------------------------------------------------------- stage loader
// A tile: 128 rows x 128B; B tile: 128 rows x 128B. XOR-swizzled 16B chunks.
__device__ __forceinline__ void issue_stage(uint32_t smStage,
                                            const __nv_bfloat16* gA,
                                            const __nv_bfloat16* gB,
                                            int kElem, int tid) {
    const char* a = (const char*)gA + (size_t)kElem * 2;
    const char* b = (const char*)gB + (size_t)kElem * 2;
#pragma unroll
    for (int i = 0; i < 4; i++) {
        int id  = tid + i * NTHREADS;      // 0..1023
        int row = id >> 3, ch = id & 7;
        uint32_t dst = smStage + row * 128 + ((ch ^ (row & 7)) << 4);
        cp16(dst, a + (size_t)row * (KC * 2) + ch * 16);
    }
#pragma unroll
    for (int i = 0; i < 4; i++) {
        int id  = tid + i * NTHREADS;
        int row = id >> 3, ch = id & 7;
        uint32_t dst = smStage + 16384 + row * 128 + ((ch ^ (row & 7)) << 4);
        cp16(dst, b + (size_t)row * (KC * 2) + ch * 16);
    }
    CP_COMMIT();
}

// ---------------------------------------------------------------- main kernel
__global__ __launch_bounds__(NTHREADS, 2)
void gmm_main(float* __restrict__ out) {
    extern __shared__ char smem[];
    uint32_t sb = smem_u32(smem);
    float* sBias = reinterpret_cast<float*>(smem + SM_BIAS_OFF);

    int tid  = threadIdx.x;
    int wid  = tid >> 5, lane = tid & 31;
    int wm   = wid & 3;          // 4 warps over M -> 32 rows each
    int wn   = wid >> 2;         // 2 warps over N -> 64 cols each

    int rowBase = blockIdx.y * BM;
    int colBase = blockIdx.x * BN;

    if (tid < BN) sBias[tid] = g_bias[colBase + tid];

    const __nv_bfloat16* gA = g_Ah + (size_t)rowBase * KC;
    const __nv_bfloat16* gB = g_Wh + (size_t)colBase * KC;

    // prologue: stages 0, 1
    issue_stage(sb + 0 * STAGE_BYTES, gA, gB, 0 * BK, tid);
    issue_stage(sb + 1 * STAGE_BYTES, gA, gB, 1 * BK, tid);

    float acc[2][8][4];
#pragma unroll
    for (int mt = 0; mt < 2; mt++)
#pragma unroll
        for (int nt = 0; nt < 8; nt++)
#pragma unroll
            for (int j = 0; j < 4; j++) acc[mt][nt][j] = 0.f;

    int rA0 = wm * 32 + (lane & 15);           // A rows for mt=0 (mt=1: +16)
    int rB0 = wn * 64 + (lane & 15);           // B rows for pair p (p: +16)
    int cHi = lane >> 4;                       // 16B-chunk parity from lane

#pragma unroll 1
    for (int s = 0; s < KITERS; s++) {
        if (s == KITERS - 1) CP_WAIT(0); else CP_WAIT(1);
        __syncthreads();

        uint32_t smA = sb + (uint32_t)(s % 3) * STAGE_BYTES;
        uint32_t smB = smA + 16384;

        if (s + 2 < KITERS)
            issue_stage(sb + (uint32_t)((s + 2) % 3) * STAGE_BYTES, gA, gB, (s + 2) * BK, tid);

#pragma unroll
        for (int ks = 0; ks < 4; ks++) {
            int c = 2 * ks + cHi;
            uint32_t a[2][4], b[4][4];
#pragma unroll
            for (int mt = 0; mt < 2; mt++) {
                int r = rA0 + mt * 16;
                LDSM4(a[mt], smA + r * 128 + ((c ^ (r & 7)) << 4));
            }
#pragma unroll
            for (int p = 0; p < 4; p++) {
                int r = rB0 + p * 16;
                LDSM4(b[p], smB + r * 128 + ((c ^ (r & 7)) << 4));
            }
#pragma unroll
            for (int mt = 0; mt < 2; mt++)
#pragma unroll
                for (int nt = 0; nt < 8; nt++) {
                    int p = nt >> 1, q = nt & 1;
                    MMA16816(acc[mt][nt], a[mt], b[p][q], b[p][q + 2]);
                }
        }
    }
    __syncthreads();

    // ------------- epilogue: bias + logsumexp over each n8 tile (= one k)
    int colq = (lane & 3) * 2;                 // this lane's 2 cols within n8
    int kBase = (colBase >> 3) + wn * 8;       // global k of nt=0
#pragma unroll
    for (int mt = 0; mt < 2; mt++) {
#pragma unroll
        for (int nt = 0; nt < 8; nt++) {
            float b0 = sBias[wn * 64 + nt * 8 + colq];
            float b1 = sBias[wn * 64 + nt * 8 + colq + 1];
#pragma unroll
            for (int h = 0; h < 2; h++) {
                float l0 = acc[mt][nt][h * 2]     + b0;
                float l1 = acc[mt][nt][h * 2 + 1] + b1;
                float m = fmaxf(l0, l1);
                m = fmaxf(m, __shfl_xor_sync(0xffffffffu, m, 1));
                m = fmaxf(m, __shfl_xor_sync(0xffffffffu, m, 2));
                float sum = fast_exp(l0 - m) + fast_exp(l1 - m);
                sum += __shfl_xor_sync(0xffffffffu, sum, 1);
                sum += __shfl_xor_sync(0xffffffffu, sum, 2);
                float res = m + fast_log(sum);
                if ((lane & 3) == 0) {
                    int row = rowBase + wm * 32 + mt * 16 + h * 8 + (lane >> 2);
                    out[(size_t)row * NK + kBase + nt] = res;
                }
            }
        }
    }
}

// ---------------------------------------------------------------- launch
extern "C" void kernel_launch(void* const* d_in, const int* in_sizes, int n_in,
                              void* d_out, int out_size) {
    const float* X       = (const float*)d_in[0];
    const float* mu      = (const float*)d_in[1];
    const float* log_cov = (const float*)d_in[2];
    const float* log_pi  = (const float*)d_in[3];
    float* out = (float*)d_out;

    cudaFuncSetAttribute(gmm_main, cudaFuncAttributeMaxDynamicSharedMemorySize, SMEM_TOTAL);

    prepA<<<(BTD * (FDIM / 4)) / 256, 256>>>(X);
    prepW<<<KLD, 256>>>(mu, log_cov);
    prepPi<<<1, 256>>>(log_pi);

    dim3 grid(KLD / BN, BTD / BM);   // (16, 256): x = N tiles, y = M tiles
    gmm_main<<<grid, NTHREADS, SMEM_TOTAL>>>(out);
}

// round 4
// speedup vs baseline: 13.4104x; 1.7024x over previous
#include <cuda_runtime.h>
#include <cuda_bf16.h>
#include <math.h>
#include <stdint.h>

// ---------------------------------------------------------------- problem dims
#define FDIM 1024
#define NK   256
#define NL   8
#define KLD  2048            // NK*NL
#define KC   2048            // full GEMM K = [X | X^2]
#define BTD  32768           // B*T

// ---------------------------------------------------------------- GEMM tiling
#define BM 128
#define BN 128
#define BK 64                // bf16 elems per K-stage (128 B per row)
#define KITERS (KC / BK)     // 32 (full), 16 when variance-uniform
#define NTHREADS 256
#define STAGES 3
#define STAGE_BYTES (32 * 1024)
#define SM_BIAS_OFF (STAGES * STAGE_BYTES)
#define SMEM_TOTAL  (SM_BIAS_OFF + 512)

// ---------------------------------------------------------------- device scratch
__device__ __nv_bfloat16 g_Ah[(size_t)BTD * KC];   // [X | X^2] bf16 (X^2 half only if !uniform)
__device__ __nv_bfloat16 g_Wh[(size_t)KLD * KC];   // [mu*iv | -0.5*iv] bf16
__device__ float         g_bias[KLD];
__device__ float         g_w2[FDIM];               // -0.5*exp(-log_cov[kl=0])  (fp32)
__device__ float         g_q[BTD];                 // per-row x^2 term when uniform, else 0
__device__ int           g_uniform;

// ---------------------------------------------------------------- asm helpers
__device__ __forceinline__ uint32_t smem_u32(const void* p) {
    uint32_t a;
    asm("{ .reg .u64 t; cvta.to.shared.u64 t, %1; cvt.u32.u64 %0, t; }" : "=r"(a) : "l"(p));
    return a;
}
__device__ __forceinline__ void cp16(uint32_t dst, const void* src) {
    asm volatile("cp.async.cg.shared.global [%0], [%1], 16;" :: "r"(dst), "l"(src));
}
#define CP_COMMIT() asm volatile("cp.async.commit_group;" ::: "memory")
#define CP_WAIT(n)  asm volatile("cp.async.wait_group %0;" :: "n"(n) : "memory")

#define LDSM4(r, addr)                                                          \
    asm volatile("ldmatrix.sync.aligned.m8n8.x4.shared.b16 {%0,%1,%2,%3}, [%4];" \
        : "=r"((r)[0]), "=r"((r)[1]), "=r"((r)[2]), "=r"((r)[3]) : "r"(addr))

#define MMA16816(c, a, b0, b1)                                                  \
    asm volatile("mma.sync.aligned.m16n8k16.row.col.f32.bf16.bf16.f32 "          \
        "{%0,%1,%2,%3}, {%4,%5,%6,%7}, {%8,%9}, {%0,%1,%2,%3};"                  \
        : "+f"((c)[0]), "+f"((c)[1]), "+f"((c)[2]), "+f"((c)[3])                 \
        : "r"((a)[0]), "r"((a)[1]), "r"((a)[2]), "r"((a)[3]), "r"(b0), "r"(b1))

// ---------------------------------------------------------------- fast math
__device__ __forceinline__ float fast_exp(float u) {   // e^u, u <= 0
    u = fmaxf(u, -60.0f);
    float z  = u * 1.4426950408889634f;
    float nf = rintf(z);
    float w  = fmaf(nf, -0.6931471805599453f, u);
    float p  = fmaf(w, 0.041666668f, 0.16666667f);
    p = fmaf(w, p, 0.5f);
    p = fmaf(w, p, 1.0f);
    p = fmaf(w, p, 1.0f);
    return p * __int_as_float(((int)nf + 127) << 23);
}
__device__ __forceinline__ float fast_log(float s) {   // ln(s), s in [1, 16]
    int ib = __float_as_int(s);
    int e  = (ib - 0x3f3504f3) >> 23;
    float m = __int_as_float(ib - (e << 23));
    float t = m - 1.0f;
    float p = -0.125f;
    p = fmaf(p, t, 0.14285714f);
    p = fmaf(p, t, -0.16666667f);
    p = fmaf(p, t, 0.2f);
    p = fmaf(p, t, -0.25f);
    p = fmaf(p, t, 0.33333333f);
    p = fmaf(p, t, -0.5f);
    p = fmaf(p, t, 1.0f);
    p = p * t;
    return fmaf((float)e, 0.6931471805599453f, p);
}

// ---------------------------------------------------------------- prep kernels
__global__ void prepW(const float* __restrict__ mu, const float* __restrict__ log_cov) {
    int kl = blockIdx.x, t = threadIdx.x;
    const float* mu_r = mu + (size_t)kl * FDIM;
    const float* lc_r = log_cov + (size_t)kl * FDIM;
    __nv_bfloat16* w_r = g_Wh + (size_t)kl * KC;
    float s_lc = 0.f, s_m2 = 0.f;
    for (int f = t; f < FDIM; f += 256) {
        float lc = lc_r[f];
        float iv = expf(-lc);
        float m  = mu_r[f];
        w_r[f]        = __float2bfloat16(m * iv);
        w_r[FDIM + f] = __float2bfloat16(-0.5f * iv);
        s_lc += lc;
        s_m2 += m * m * iv;
    }
    __shared__ float sh0[256], sh1[256];
    sh0[t] = s_lc; sh1[t] = s_m2;
    __syncthreads();
    for (int s = 128; s > 0; s >>= 1) {
        if (t < s) { sh0[t] += sh0[t + s]; sh1[t] += sh1[t + s]; }
        __syncthreads();
    }
    if (t == 0)
        g_bias[kl] = -0.5f * (float)FDIM * 1.8378770664093453f - 0.5f * sh0[0] - 0.5f * sh1[0];
}

__global__ void initFlagW2(const float* __restrict__ log_cov) {
    int f = blockIdx.x * blockDim.x + threadIdx.x;      // FDIM threads
    if (f == 0) g_uniform = 1;
    g_w2[f] = -0.5f * expf(-log_cov[f]);                // row kl=0
}

// Is the -0.5*iv (bf16) row identical for all kl?  (bitwise on the GEMM operand)
__global__ void checkUni() {
    int kl = blockIdx.x + 1;
    const uint32_t* a = reinterpret_cast<const uint32_t*>(g_Wh + (size_t)kl * KC + FDIM);
    const uint32_t* b = reinterpret_cast<const uint32_t*>(g_Wh + FDIM);
    int t = threadIdx.x;
    bool ok = (a[t] == b[t]) && (a[t + 256] == b[t + 256]);
    if (!__syncthreads_and(ok)) {
        if (t == 0) atomicAnd(&g_uniform, 0);
    }
}

__global__ void prepPi(const float* __restrict__ log_pi) {
    int k = blockIdx.x * blockDim.x + threadIdx.x;
    if (k >= NK) return;
    float v[NL], mx = -INFINITY;
#pragma unroll
    for (int l = 0; l < NL; l++) { v[l] = log_pi[k * NL + l]; mx = fmaxf(mx, v[l]); }
    float s = 0.f;
#pragma unroll
    for (int l = 0; l < NL; l++) s += expf(v[l] - mx);
    float lse = mx + logf(s);
#pragma unroll
    for (int l = 0; l < NL; l++) g_bias[k * NL + l] += v[l] - lse;
}

// One block per row: write bf16 X (+ X^2 if needed) and reduce q[row].
__global__ void prepA(const float* __restrict__ X) {
    int row = blockIdx.x, t = threadIdx.x;
    bool uni = (g_uniform != 0);
    float4 v = reinterpret_cast<const float4*>(X)[(size_t)row * 256 + t];
    __nv_bfloat16* a = g_Ah + (size_t)row * KC;
    int c = t * 4;
    *reinterpret_cast<__nv_bfloat162*>(a + c)     = __floats2bfloat162_rn(v.x, v.y);
    *reinterpret_cast<__nv_bfloat162*>(a + c + 2) = __floats2bfloat162_rn(v.z, v.w);
    float q = 0.f;
    if (uni) {
        const float4 w = reinterpret_cast<const float4*>(g_w2)[t];
        q = v.x * v.x * w.x + v.y * v.y * w.y + v.z * v.z * w.z + v.w * v.w * w.w;
    } else {
        *reinterpret_cast<__nv_bfloat162*>(a + FDIM + c)     = __floats2bfloat162_rn(v.x * v.x, v.y * v.y);
        *reinterpret_cast<__nv_bfloat162*>(a + FDIM + c + 2) = __floats2bfloat162_rn(v.z * v.z, v.w * v.w);
    }
    // block reduce q
#pragma unroll
    for (int o = 16; o > 0; o >>= 1) q += __shfl_xor_sync(0xffffffffu, q, o);
    __shared__ float sh[8];
    if ((t & 31) == 0) sh[t >> 5] = q;
    __syncthreads();
    if (t == 0) {
        float s = 0.f;
#pragma unroll
        for (int w = 0; w < 8; w++) s += sh[w];
        g_q[row] = s;   // 0 when !uni (q stayed 0)
    }
}

// ---------------------------------------------------------------- stage loader
__device__ __forceinline__ void issue_stage(uint32_t smStage,
                                            const __nv_bfloat16* gA,
                                            const __nv_bfloat16* gB,
                                            int kElem, int tid) {
    const char* a = (const char*)gA + (size_t)kElem * 2;
    const char* b = (const char*)gB + (size_t)kElem * 2;
#pragma unroll
    for (int i = 0; i < 4; i++) {
        int id  = tid + i * NTHREADS;
        int row = id >> 3, ch = id & 7;
        uint32_t dst = smStage + row * 128 + ((ch ^ (row & 7)) << 4);
        cp16(dst, a + (size_t)row * (KC * 2) + ch * 16);
    }
#pragma unroll
    for (int i = 0; i < 4; i++) {
        int id  = tid + i * NTHREADS;
        int row = id >> 3, ch = id & 7;
        uint32_t dst = smStage + 16384 + row * 128 + ((ch ^ (row & 7)) << 4);
        cp16(dst, b + (size_t)row * (KC * 2) + ch * 16);
    }
    CP_COMMIT();
}

// ---------------------------------------------------------------- main kernel
__global__ __launch_bounds__(NTHREADS, 2)
void gmm_main(float* __restrict__ out) {
    extern __shared__ char smem[];
    uint32_t sb = smem_u32(smem);
    float* sBias = reinterpret_cast<float*>(smem + SM_BIAS_OFF);

    int tid  = threadIdx.x;
    int wid  = tid >> 5, lane = tid & 31;
    int wm   = wid & 3;
    int wn   = wid >> 2;

    int rowBase = blockIdx.y * BM;
    int colBase = blockIdx.x * BN;
    int kIters  = (g_uniform != 0) ? (KITERS / 2) : KITERS;

    if (tid < BN) sBias[tid] = g_bias[colBase + tid];

    const __nv_bfloat16* gA = g_Ah + (size_t)rowBase * KC;
    const __nv_bfloat16* gB = g_Wh + (size_t)colBase * KC;

    issue_stage(sb + 0 * STAGE_BYTES, gA, gB, 0 * BK, tid);
    issue_stage(sb + 1 * STAGE_BYTES, gA, gB, 1 * BK, tid);

    float acc[2][8][4];
#pragma unroll
    for (int mt = 0; mt < 2; mt++)
#pragma unroll
        for (int nt = 0; nt < 8; nt++)
#pragma unroll
            for (int j = 0; j < 4; j++) acc[mt][nt][j] = 0.f;

    // per-lane swizzled base offsets (XOR-composable with ks<<5)
    int cHi = lane >> 4;
    uint32_t offA[2], offB[4];
#pragma unroll
    for (int mt = 0; mt < 2; mt++) {
        int r = wm * 32 + (lane & 15) + mt * 16;
        offA[mt] = (uint32_t)(r * 128) + (uint32_t)(((cHi ^ (r & 7))) << 4);
    }
#pragma unroll
    for (int p = 0; p < 4; p++) {
        int r = wn * 64 + (lane & 15) + p * 16;
        offB[p] = (uint32_t)(16384 + r * 128) + (uint32_t)(((cHi ^ (r & 7))) << 4);
    }

#pragma unroll 1
    for (int s = 0; s < kIters; s++) {
        if (s == kIters - 1) CP_WAIT(0); else CP_WAIT(1);
        __syncthreads();

        uint32_t smStage = sb + (uint32_t)(s % 3) * STAGE_BYTES;

        if (s + 2 < kIters)
            issue_stage(sb + (uint32_t)((s + 2) % 3) * STAGE_BYTES, gA, gB, (s + 2) * BK, tid);

        uint32_t baseA0 = smStage + offA[0];
        uint32_t baseA1 = smStage + offA[1];
        uint32_t baseB0 = smStage + offB[0];
        uint32_t baseB1 = smStage + offB[1];
        uint32_t baseB2 = smStage + offB[2];
        uint32_t baseB3 = smStage + offB[3];

#pragma unroll
        for (int ks = 0; ks < 4; ks++) {
            uint32_t kx = (uint32_t)ks << 5;
            uint32_t a[2][4], b[4][4];
            LDSM4(a[0], baseA0 ^ kx);
            LDSM4(a[1], baseA1 ^ kx);
            LDSM4(b[0], baseB0 ^ kx);
            LDSM4(b[1], baseB1 ^ kx);
            LDSM4(b[2], baseB2 ^ kx);
            LDSM4(b[3], baseB3 ^ kx);
#pragma unroll
            for (int mt = 0; mt < 2; mt++)
#pragma unroll
                for (int nt = 0; nt < 8; nt++) {
                    int p = nt >> 1, q = nt & 1;
                    MMA16816(acc[mt][nt], a[mt], b[p][q], b[p][q + 2]);
                }
        }
    }
    __syncthreads();

    // ------------- epilogue: bias + logsumexp(8) + q[row]
    int colq = (lane & 3) * 2;
    int kBase = (colBase >> 3) + wn * 8;
#pragma unroll
    for (int mt = 0; mt < 2; mt++) {
#pragma unroll
        for (int nt = 0; nt < 8; nt++) {
            float b0 = sBias[wn * 64 + nt * 8 + colq];
            float b1 = sBias[wn * 64 + nt * 8 + colq + 1];
#pragma unroll
            for (int h = 0; h < 2; h++) {
                float l0 = acc[mt][nt][h * 2]     + b0;
                float l1 = acc[mt][nt][h * 2 + 1] + b1;
                float m = fmaxf(l0, l1);
                m = fmaxf(m, __shfl_xor_sync(0xffffffffu, m, 1));
                m = fmaxf(m, __shfl_xor_sync(0xffffffffu, m, 2));
                float sum = fast_exp(l0 - m) + fast_exp(l1 - m);
                sum += __shfl_xor_sync(0xffffffffu, sum, 1);
                sum += __shfl_xor_sync(0xffffffffu, sum, 2);
                if ((lane & 3) == 0) {
                    int row = rowBase + wm * 32 + mt * 16 + h * 8 + (lane >> 2);
                    float res = m + fast_log(sum) + g_q[row];
                    out[(size_t)row * NK + kBase + nt] = res;
                }
            }
        }
    }
}

// ---------------------------------------------------------------- launch
extern "C" void kernel_launch(void* const* d_in, const int* in_sizes, int n_in,
                              void* d_out, int out_size) {
    const float* X       = (const float*)d_in[0];
    const float* mu      = (const float*)d_in[1];
    const float* log_cov = (const float*)d_in[2];
    const float* log_pi  = (const float*)d_in[3];
    float* out = (float*)d_out;

    cudaFuncSetAttribute(gmm_main, cudaFuncAttributeMaxDynamicSharedMemorySize, SMEM_TOTAL);

    prepW<<<KLD, 256>>>(mu, log_cov);
    initFlagW2<<<FDIM / 256, 256>>>(log_cov);
    checkUni<<<KLD - 1, 256>>>();
    prepA<<<BTD, 256>>>(X);
    prepPi<<<1, 256>>>(log_pi);

    dim3 grid(KLD / BN, BTD / BM);   // (16, 256)
    gmm_main<<<grid, NTHREADS, SMEM_TOTAL>>>(out);
}

// round 5
// speedup vs baseline: 20.2139x; 1.5073x over previous
#include <cuda_runtime.h>
#include <cuda_bf16.h>
#include <math.h>
#include <stdint.h>

// ---------------------------------------------------------------- problem dims
#define FDIM 1024
#define NK   256
#define NL   8
#define KLD  2048            // NK*NL
#define BTD  32768           // B*T
#define KCB  2048            // row stride in BYTES of quantized A/W ([x | x^2] int8)

// ---------------------------------------------------------------- GEMM tiling
#define BM 128
#define BN 128
#define BKB 128              // K-bytes per stage (= 128 int8 k-elems)
#define NTHREADS 256
#define STAGES 3
#define STAGE_BYTES (32 * 1024)           // A 16KB + B 16KB
#define SM_BIAS_OFF (STAGES * STAGE_BYTES)
#define SM_SW_OFF   (SM_BIAS_OFF + BN * 4)
#define SMEM_TOTAL  (SM_SW_OFF + BN * 4)

#define ALPHA 8.0f           // scale equalizer for the x^2 half (fallback path)

// ---------------------------------------------------------------- device scratch
__device__ int8_t g_Aq[(size_t)BTD * KCB];   // 64 MB  [x_q | x2_q]
__device__ int8_t g_Wq[(size_t)KLD * KCB];   // 4 MB   [w_q | w2_q]
__device__ float  g_bias[KLD];
__device__ float  g_sW[KLD];                 // per-(k,l) W scale
__device__ float  g_sA[BTD];                 // per-row X scale
__device__ float  g_w2[FDIM];                // -0.5*exp(-log_cov[0][f]) fp32
__device__ float  g_q[BTD];                  // per-row x^2 term when uniform
__device__ int    g_uniform;

// ---------------------------------------------------------------- asm helpers
__device__ __forceinline__ uint32_t smem_u32(const void* p) {
    uint32_t a;
    asm("{ .reg .u64 t; cvta.to.shared.u64 t, %1; cvt.u32.u64 %0, t; }" : "=r"(a) : "l"(p));
    return a;
}
__device__ __forceinline__ void cp16(uint32_t dst, const void* src) {
    asm volatile("cp.async.cg.shared.global [%0], [%1], 16;" :: "r"(dst), "l"(src));
}
#define CP_COMMIT() asm volatile("cp.async.commit_group;" ::: "memory")
#define CP_WAIT(n)  asm volatile("cp.async.wait_group %0;" :: "n"(n) : "memory")

#define LDSM4(r, addr)                                                           \
    asm volatile("ldmatrix.sync.aligned.m8n8.x4.shared.b16 {%0,%1,%2,%3}, [%4];" \
        : "=r"((r)[0]), "=r"((r)[1]), "=r"((r)[2]), "=r"((r)[3]) : "r"(addr))

#define MMAI8(c, a, b0, b1)                                                      \
    asm volatile("mma.sync.aligned.m16n8k32.row.col.s32.s8.s8.s32 "              \
        "{%0,%1,%2,%3}, {%4,%5,%6,%7}, {%8,%9}, {%0,%1,%2,%3};"                  \
        : "+r"((c)[0]), "+r"((c)[1]), "+r"((c)[2]), "+r"((c)[3])                 \
        : "r"((a)[0]), "r"((a)[1]), "r"((a)[2]), "r"((a)[3]), "r"(b0), "r"(b1))

// ---------------------------------------------------------------- fast math
__device__ __forceinline__ float fast_exp(float u) {   // e^u, u <= 0
    u = fmaxf(u, -60.0f);
    float z  = u * 1.4426950408889634f;
    float nf = rintf(z);
    float w  = fmaf(nf, -0.6931471805599453f, u);
    float p  = fmaf(w, 0.041666668f, 0.16666667f);
    p = fmaf(w, p, 0.5f);
    p = fmaf(w, p, 1.0f);
    p = fmaf(w, p, 1.0f);
    return p * __int_as_float(((int)nf + 127) << 23);
}
__device__ __forceinline__ float fast_log(float s) {   // ln(s), s in [1, 16]
    int ib = __float_as_int(s);
    int e  = (ib - 0x3f3504f3) >> 23;
    float m = __int_as_float(ib - (e << 23));
    float t = m - 1.0f;
    float p = -0.125f;
    p = fmaf(p, t, 0.14285714f);
    p = fmaf(p, t, -0.16666667f);
    p = fmaf(p, t, 0.2f);
    p = fmaf(p, t, -0.25f);
    p = fmaf(p, t, 0.33333333f);
    p = fmaf(p, t, -0.5f);
    p = fmaf(p, t, 1.0f);
    p = p * t;
    return fmaf((float)e, 0.6931471805599453f, p);
}

__device__ __forceinline__ int8_t q8(float v, float inv) {
    int q = __float2int_rn(v * inv);
    q = max(-127, min(127, q));
    return (int8_t)q;
}
__device__ __forceinline__ uint32_t pack4(int8_t a, int8_t b, int8_t c, int8_t d) {
    return (uint32_t)(uint8_t)a | ((uint32_t)(uint8_t)b << 8) |
           ((uint32_t)(uint8_t)c << 16) | ((uint32_t)(uint8_t)d << 24);
}

// ---------------------------------------------------------------- prep kernels
__global__ void initFlagW2(const float* __restrict__ log_cov) {
    int f = blockIdx.x * blockDim.x + threadIdx.x;
    if (f == 0) g_uniform = 1;
    g_w2[f] = -0.5f * expf(-log_cov[f]);
}

// uniform iff every log_cov row is bitwise identical to row 0
__global__ void checkUni(const float* __restrict__ log_cov) {
    int kl = blockIdx.x + 1, t = threadIdx.x;
    const uint4* a = reinterpret_cast<const uint4*>(log_cov + (size_t)kl * FDIM);
    const uint4* b = reinterpret_cast<const uint4*>(log_cov);
    uint4 x = a[t], y = b[t];
    bool ok = (x.x == y.x) && (x.y == y.y) && (x.z == y.z) && (x.w == y.w);
    if (!__syncthreads_and(ok)) {
        if (t == 0) atomicAnd(&g_uniform, 0);
    }
}

// per (k,l): quantize w = mu*iv (and w2 = -0.5*iv if fallback), bias pieces.
__global__ void prepW(const float* __restrict__ mu, const float* __restrict__ log_cov) {
    int kl = blockIdx.x, t = threadIdx.x;
    bool uni = (g_uniform != 0);
    const float* mu_r = mu + (size_t)kl * FDIM;
    const float* lc_r = log_cov + (size_t)kl * FDIM;
    int8_t* wq = g_Wq + (size_t)kl * KCB;

    float w[4], w2[4];
    float s_lc = 0.f, s_m2 = 0.f, am = 0.f;
#pragma unroll
    for (int j = 0; j < 4; j++) {
        int f = t * 4 + j;
        float lc = lc_r[f];
        float iv = expf(-lc);
        float m  = mu_r[f];
        w[j]  = m * iv;
        w2[j] = -0.5f * iv;
        s_lc += lc;
        s_m2 += m * m * iv;
        am = fmaxf(am, fabsf(w[j]));
    }
    // block reduce: sums + absmax
    __shared__ float sh0[256], sh1[256], shm[256];
    sh0[t] = s_lc; sh1[t] = s_m2; shm[t] = am;
    __syncthreads();
    for (int s = 128; s > 0; s >>= 1) {
        if (t < s) {
            sh0[t] += sh0[t + s];
            sh1[t] += sh1[t + s];
            shm[t] = fmaxf(shm[t], shm[t + s]);
        }
        __syncthreads();
    }
    float absmax = fmaxf(shm[0], 1e-20f);
    float sw = absmax / 127.0f;
    float inv = 127.0f / absmax;
    *reinterpret_cast<uint32_t*>(wq + t * 4) =
        pack4(q8(w[0], inv), q8(w[1], inv), q8(w[2], inv), q8(w[3], inv));
    if (!uni) {
        float inv2 = inv * ALPHA;   // w2_q = w2 * ALPHA / sw
        *reinterpret_cast<uint32_t*>(wq + FDIM + t * 4) =
            pack4(q8(w2[0], inv2), q8(w2[1], inv2), q8(w2[2], inv2), q8(w2[3], inv2));
    }
    if (t == 0) {
        g_sW[kl] = sw;
        g_bias[kl] = -0.5f * (float)FDIM * 1.8378770664093453f - 0.5f * sh0[0] - 0.5f * sh1[0];
    }
}

__global__ void prepPi(const float* __restrict__ log_pi) {
    int k = blockIdx.x * blockDim.x + threadIdx.x;
    if (k >= NK) return;
    float v[NL], mx = -INFINITY;
#pragma unroll
    for (int l = 0; l < NL; l++) { v[l] = log_pi[k * NL + l]; mx = fmaxf(mx, v[l]); }
    float s = 0.f;
#pragma unroll
    for (int l = 0; l < NL; l++) s += expf(v[l] - mx);
    float lse = mx + logf(s);
#pragma unroll
    for (int l = 0; l < NL; l++) g_bias[k * NL + l] += v[l] - lse;
}

// one block per row: absmax -> quantize X (+ X^2 if fallback), q[row], scale
__global__ void prepA(const float* __restrict__ X) {
    int row = blockIdx.x, t = threadIdx.x;
    bool uni = (g_uniform != 0);
    float4 v = reinterpret_cast<const float4*>(X)[(size_t)row * 256 + t];
    float am = fmaxf(fmaxf(fabsf(v.x), fabsf(v.y)), fmaxf(fabsf(v.z), fabsf(v.w)));
#pragma unroll
    for (int o = 16; o > 0; o >>= 1) am = fmaxf(am, __shfl_xor_sync(0xffffffffu, am, o));
    __shared__ float shm[8];
    __shared__ float shq[8];
    if ((t & 31) == 0) shm[t >> 5] = am;
    __syncthreads();
    float absmax = 1e-20f;
#pragma unroll
    for (int w = 0; w < 8; w++) absmax = fmaxf(absmax, shm[w]);
    float inv = 127.0f / absmax;

    int8_t* aq = g_Aq + (size_t)row * KCB;
    *reinterpret_cast<uint32_t*>(aq + t * 4) =
        pack4(q8(v.x, inv), q8(v.y, inv), q8(v.z, inv), q8(v.w, inv));

    float q = 0.f;
    if (uni) {
        const float4 w = reinterpret_cast<const float4*>(g_w2)[t];
        q = v.x * v.x * w.x + v.y * v.y * w.y + v.z * v.z * w.z + v.w * v.w * w.w;
    } else {
        float inv2 = inv / ALPHA;   // x2_q = x^2 / (ALPHA * sxr)
        *reinterpret_cast<uint32_t*>(aq + FDIM + t * 4) =
            pack4(q8(v.x * v.x, inv2), q8(v.y * v.y, inv2),
                  q8(v.z * v.z, inv2), q8(v.w * v.w, inv2));
    }
#pragma unroll
    for (int o = 16; o > 0; o >>= 1) q += __shfl_xor_sync(0xffffffffu, q, o);
    if ((t & 31) == 0) shq[t >> 5] = q;
    __syncthreads();
    if (t == 0) {
        float s = 0.f;
#pragma unroll
        for (int w = 0; w < 8; w++) s += shq[w];
        g_q[row] = s;
        g_sA[row] = absmax / 127.0f;
    }
}

// ---------------------------------------------------------------- stage loader
// A tile: 128 rows x 128B; B tile: 128 rows x 128B. XOR-swizzled 16B chunks.
__device__ __forceinline__ void issue_stage(uint32_t smStage,
                                            const int8_t* gA, const int8_t* gB,
                                            int kByte, int tid) {
    const int8_t* a = gA + kByte;
    const int8_t* b = gB + kByte;
#pragma unroll
    for (int i = 0; i < 4; i++) {
        int id  = tid + i * NTHREADS;
        int row = id >> 3, ch = id & 7;
        uint32_t dst = smStage + row * 128 + ((ch ^ (row & 7)) << 4);
        cp16(dst, a + (size_t)row * KCB + ch * 16);
    }
#pragma unroll
    for (int i = 0; i < 4; i++) {
        int id  = tid + i * NTHREADS;
        int row = id >> 3, ch = id & 7;
        uint32_t dst = smStage + 16384 + row * 128 + ((ch ^ (row & 7)) << 4);
        cp16(dst, b + (size_t)row * KCB + ch * 16);
    }
    CP_COMMIT();
}

// ---------------------------------------------------------------- main kernel
__global__ __launch_bounds__(NTHREADS, 2)
void gmm_main(float* __restrict__ out) {
    extern __shared__ char smem[];
    uint32_t sb = smem_u32(smem);
    float* sBias = reinterpret_cast<float*>(smem + SM_BIAS_OFF);
    float* sSw   = reinterpret_cast<float*>(smem + SM_SW_OFF);

    int tid  = threadIdx.x;
    int wid  = tid >> 5, lane = tid & 31;
    int wm   = wid & 3;
    int wn   = wid >> 2;

    int rowBase = blockIdx.y * BM;
    int colBase = blockIdx.x * BN;
    int kIters  = (g_uniform != 0) ? 8 : 16;   // K bytes / BKB

    if (tid < BN) {
        sBias[tid] = g_bias[colBase + tid];
        sSw[tid]   = g_sW[colBase + tid];
    }

    const int8_t* gA = g_Aq + (size_t)rowBase * KCB;
    const int8_t* gB = g_Wq + (size_t)colBase * KCB;

    issue_stage(sb + 0 * STAGE_BYTES, gA, gB, 0 * BKB, tid);
    issue_stage(sb + 1 * STAGE_BYTES, gA, gB, 1 * BKB, tid);

    int acc[2][8][4];
#pragma unroll
    for (int mt = 0; mt < 2; mt++)
#pragma unroll
        for (int nt = 0; nt < 8; nt++)
#pragma unroll
            for (int j = 0; j < 4; j++) acc[mt][nt][j] = 0;

    // per-lane swizzled base offsets (XOR-composable with ks<<5)
    int cHi = lane >> 4;
    uint32_t offA[2], offB[4];
#pragma unroll
    for (int mt = 0; mt < 2; mt++) {
        int r = wm * 32 + (lane & 15) + mt * 16;
        offA[mt] = (uint32_t)(r * 128) + (uint32_t)(((cHi ^ (r & 7))) << 4);
    }
#pragma unroll
    for (int p = 0; p < 4; p++) {
        int r = wn * 64 + (lane & 15) + p * 16;
        offB[p] = (uint32_t)(16384 + r * 128) + (uint32_t)(((cHi ^ (r & 7))) << 4);
    }

#pragma unroll 1
    for (int s = 0; s < kIters; s++) {
        if (s == kIters - 1) CP_WAIT(0); else CP_WAIT(1);
        __syncthreads();

        uint32_t smStage = sb + (uint32_t)(s % 3) * STAGE_BYTES;

        if (s + 2 < kIters)
            issue_stage(sb + (uint32_t)((s + 2) % 3) * STAGE_BYTES, gA, gB, (s + 2) * BKB, tid);

        uint32_t baseA0 = smStage + offA[0];
        uint32_t baseA1 = smStage + offA[1];
        uint32_t baseB0 = smStage + offB[0];
        uint32_t baseB1 = smStage + offB[1];
        uint32_t baseB2 = smStage + offB[2];
        uint32_t baseB3 = smStage + offB[3];

#pragma unroll
        for (int ks = 0; ks < 4; ks++) {       // each ks = 32 int8 k-elems
            uint32_t kx = (uint32_t)ks << 5;
            uint32_t a[2][4], b[4][4];
            LDSM4(a[0], baseA0 ^ kx);
            LDSM4(a[1], baseA1 ^ kx);
            LDSM4(b[0], baseB0 ^ kx);
            LDSM4(b[1], baseB1 ^ kx);
            LDSM4(b[2], baseB2 ^ kx);
            LDSM4(b[3], baseB3 ^ kx);
#pragma unroll
            for (int mt = 0; mt < 2; mt++)
#pragma unroll
                for (int nt = 0; nt < 8; nt++) {
                    int p = nt >> 1, q = nt & 1;
                    MMAI8(acc[mt][nt], a[mt], b[p][q], b[p][q + 2]);
                }
        }
    }
    __syncthreads();

    // ------------- epilogue: dequant + bias + logsumexp(8) + q[row]
    int colq = (lane & 3) * 2;
    int kBase = (colBase >> 3) + wn * 8;
#pragma unroll
    for (int mt = 0; mt < 2; mt++) {
#pragma unroll
        for (int h = 0; h < 2; h++) {
            int row = rowBase + wm * 32 + mt * 16 + h * 8 + (lane >> 2);
            float sxr = g_sA[row];
            float qr  = g_q[row];
#pragma unroll
            for (int nt = 0; nt < 8; nt++) {
                int c0 = wn * 64 + nt * 8 + colq;
                float sc0 = sSw[c0] * sxr;
                float sc1 = sSw[c0 + 1] * sxr;
                float l0 = (float)acc[mt][nt][h * 2]     * sc0 + sBias[c0];
                float l1 = (float)acc[mt][nt][h * 2 + 1] * sc1 + sBias[c0 + 1];
                float m = fmaxf(l0, l1);
                m = fmaxf(m, __shfl_xor_sync(0xffffffffu, m, 1));
                m = fmaxf(m, __shfl_xor_sync(0xffffffffu, m, 2));
                float sum = fast_exp(l0 - m) + fast_exp(l1 - m);
                sum += __shfl_xor_sync(0xffffffffu, sum, 1);
                sum += __shfl_xor_sync(0xffffffffu, sum, 2);
                if ((lane & 3) == 0)
                    out[(size_t)row * NK + kBase + nt] = m + fast_log(sum) + qr;
            }
        }
    }
}

// ---------------------------------------------------------------- launch
extern "C" void kernel_launch(void* const* d_in, const int* in_sizes, int n_in,
                              void* d_out, int out_size) {
    const float* X       = (const float*)d_in[0];
    const float* mu      = (const float*)d_in[1];
    const float* log_cov = (const float*)d_in[2];
    const float* log_pi  = (const float*)d_in[3];
    float* out = (float*)d_out;

    cudaFuncSetAttribute(gmm_main, cudaFuncAttributeMaxDynamicSharedMemorySize, SMEM_TOTAL);

    initFlagW2<<<FDIM / 256, 256>>>(log_cov);
    checkUni<<<KLD - 1, 256>>>(log_cov);
    prepW<<<KLD, 256>>>(mu, log_cov);
    prepA<<<BTD, 256>>>(X);
    prepPi<<<1, 256>>>(log_pi);

    dim3 grid(KLD / BN, BTD / BM);   // (16, 256)
    gmm_main<<<grid, NTHREADS, SMEM_TOTAL>>>(out);
}